// round 3
// baseline (speedup 1.0000x reference)
#include <cuda_runtime.h>
#include <cstdint>
#include <cstddef>

// x_{t+1} = x_t + 0.1*tanh([x_t,u_t]@W1 + b1)@W2 + b2
// B=1024, T=200, SD=64, CD=32, H=512. Persistent CTA per 8 batch rows.

typedef unsigned long long u64;

static constexpr int   TSTEPS = 200;
static constexpr int   SDIM   = 64;
static constexpr int   CDIM   = 32;
static constexpr int   INDIM  = 96;
static constexpr int   HDIM   = 512;
static constexpr int   ROWS   = 8;
static constexpr int   NBLK   = 1024 / ROWS;   // 128
static constexpr int   NTHR   = 256;
static constexpr int   HPAD   = 516;           // h row stride in u64
static constexpr float DTC    = 0.1f;

static constexpr int W2_DBL = HDIM * SDIM / 2;   // 16384 u64 (W2 as f32x2 pairs)
static constexpr int HD_DBL = ROWS * HPAD;       //  4128 u64 (h duplicated {h,h})
static constexpr int IN_DBL = INDIM * ROWS;      //   768 u64 ([x,u] duplicated)
static constexpr int PS_DBL = 16 * ROWS * 32;    //  4096 u64 (phase-B partials)
static constexpr size_t SMEM_BYTES =
    (size_t)(W2_DBL + HD_DBL + IN_DBL + PS_DBL) * 8 + (size_t)SDIM * 4;  // 203264

__device__ __forceinline__ u64 ffma2(u64 a, u64 b, u64 c) {
    u64 d;
    asm("fma.rn.f32x2 %0, %1, %2, %3;" : "=l"(d) : "l"(a), "l"(b), "l"(c));
    return d;
}
__device__ __forceinline__ u64 fadd2(u64 a, u64 b) {
    u64 d;
    asm("add.rn.f32x2 %0, %1, %2;" : "=l"(d) : "l"(a), "l"(b));
    return d;
}
__device__ __forceinline__ u64 pack2(float lo, float hi) {
    u64 d;
    asm("mov.b64 %0, {%1, %2};" : "=l"(d) : "r"(__float_as_int(lo)), "r"(__float_as_int(hi)));
    return d;
}
__device__ __forceinline__ float2 unpack2(u64 d) {
    int lo, hi;
    asm("mov.b64 {%0, %1}, %2;" : "=r"(lo), "=r"(hi) : "l"(d));
    return make_float2(__int_as_float(lo), __int_as_float(hi));
}

__device__ __forceinline__ float fast_tanh(float x) {
    float e = __expf(2.0f * x);
    return 1.0f - __fdividef(2.0f, e + 1.0f);
}

__global__ void __launch_bounds__(NTHR, 1)
rollout_kernel(const float* __restrict__ x0,
               const float* __restrict__ controls,
               const float* __restrict__ W1,
               const float* __restrict__ b1,
               const float* __restrict__ W2,
               const float* __restrict__ b2,
               float* __restrict__ out)
{
    extern __shared__ unsigned char smem_raw[];
    u64* W2d  = (u64*)smem_raw;               // [HDIM][32] packed pairs (i,i+1)
    u64* h_d  = W2d + W2_DBL;                 // [ROWS][HPAD] {h,h}
    u64* in_d = h_d + HD_DBL;                 // [INDIM][ROWS] {v,v}
    u64* psd  = in_d + IN_DBL;                // [16][ROWS][32]
    float* b2s = (float*)(psd + PS_DBL);      // [SDIM]

    const int tid  = threadIdx.x;
    const int lane = tid & 31;
    const int b0   = blockIdx.x * ROWS;

    const int rp = tid >> 6;   // phase A: row pair 0..3
    const int ct = tid & 63;   // phase A: col group 0..63 (8 cols)
    const int ks = tid >> 4;   // phase B: k-split 0..15
    const int ig = tid & 15;   // phase B: i group 0..15 (4 i's)
    const int rr = tid >> 5;   // epilogue / staging row 0..7

    // ---- prologue: W2 -> smem, b2 -> smem ----
    {
        const float4* src = (const float4*)W2;
        float4* dst = (float4*)W2d;
        #pragma unroll
        for (int i = tid; i < (HDIM * SDIM) / 4; i += NTHR) dst[i] = src[i];
    }
    if (tid < SDIM) b2s[tid] = b2[tid];

    // b1 pairs for this thread's 8 columns
    u64 b1d[4];
    {
        const u64* b1p = (const u64*)b1;
        b1d[0] = b1p[ct * 2];
        b1d[1] = b1p[ct * 2 + 1];
        b1d[2] = b1p[128 + ct * 2];
        b1d[3] = b1p[128 + ct * 2 + 1];
    }

    // stage x0 and u(0); emit states[:, 0, :]
    {
        const int gb = b0 + rr;
        float xa = x0[gb * SDIM + lane];
        float xb = x0[gb * SDIM + lane + 32];
        in_d[lane * ROWS + rr]        = pack2(xa, xa);
        in_d[(lane + 32) * ROWS + rr] = pack2(xb, xb);
        size_t ob = (size_t)gb * (TSTEPS + 1) * SDIM;
        out[ob + lane]      = xa;
        out[ob + lane + 32] = xb;
        float u = controls[(size_t)gb * TSTEPS * CDIM + lane];
        in_d[(SDIM + lane) * ROWS + rr] = pack2(u, u);
    }
    __syncthreads();

    const ulonglong2* in2 = (const ulonglong2*)in_d;   // [k*4 + rp]
    const ulonglong2* W1d = (const ulonglong2*)W1;     // row k = 128 ulonglong2
    const ulonglong2* W2v = (const ulonglong2*)W2d;    // [k*16 + ig]

    for (int t = 0; t < TSTEPS; ++t) {
        // prefetch next-step control (consumed in epilogue, long latency hidden)
        float u_next = 0.0f;
        if (t + 1 < TSTEPS)
            u_next = controls[(size_t)(b0 + rr) * TSTEPS * CDIM
                              + (size_t)(t + 1) * CDIM + lane];

        // ---- Phase A: h = tanh(in @ W1 + b1); 2 rows x 8 cols/thread ----
        u64 acc[8];
        acc[0] = b1d[0]; acc[1] = b1d[1]; acc[2] = b1d[2]; acc[3] = b1d[3];
        acc[4] = b1d[0]; acc[5] = b1d[1]; acc[6] = b1d[2]; acc[7] = b1d[3];
        #pragma unroll 4
        for (int k = 0; k < INDIM; ++k) {
            ulonglong2 uu = in2[k * 4 + rp];
            ulonglong2 wa = W1d[k * 128 + ct];
            ulonglong2 wb = W1d[k * 128 + 64 + ct];
            acc[0] = ffma2(wa.x, uu.x, acc[0]);
            acc[1] = ffma2(wa.y, uu.x, acc[1]);
            acc[2] = ffma2(wb.x, uu.x, acc[2]);
            acc[3] = ffma2(wb.y, uu.x, acc[3]);
            acc[4] = ffma2(wa.x, uu.y, acc[4]);
            acc[5] = ffma2(wa.y, uu.y, acc[5]);
            acc[6] = ffma2(wb.x, uu.y, acc[6]);
            acc[7] = ffma2(wb.y, uu.y, acc[7]);
        }
        {
            u64* h0 = h_d + (rp * 2) * HPAD;
            u64* h1 = h0 + HPAD;
            #pragma unroll
            for (int q = 0; q < 2; ++q) {
                int jb = (q == 0) ? (ct * 4) : (256 + ct * 4);
                float2 v0 = unpack2(acc[q * 2 + 0]);
                float2 v1 = unpack2(acc[q * 2 + 1]);
                float2 v2 = unpack2(acc[4 + q * 2 + 0]);
                float2 v3 = unpack2(acc[4 + q * 2 + 1]);
                float t0 = fast_tanh(v0.x), t1 = fast_tanh(v0.y);
                float t2 = fast_tanh(v1.x), t3 = fast_tanh(v1.y);
                float s0 = fast_tanh(v2.x), s1 = fast_tanh(v2.y);
                float s2 = fast_tanh(v3.x), s3 = fast_tanh(v3.y);
                *(ulonglong2*)(h0 + jb)     = make_ulonglong2(pack2(t0, t0), pack2(t1, t1));
                *(ulonglong2*)(h0 + jb + 2) = make_ulonglong2(pack2(t2, t2), pack2(t3, t3));
                *(ulonglong2*)(h1 + jb)     = make_ulonglong2(pack2(s0, s0), pack2(s1, s1));
                *(ulonglong2*)(h1 + jb + 2) = make_ulonglong2(pack2(s2, s2), pack2(s3, s3));
            }
        }
        __syncthreads();

        // ---- Phase B: partials of h @ W2; 8 rows x 4 i's/thread, 16-way k split ----
        u64 accB[16];
        #pragma unroll
        for (int q = 0; q < 16; ++q) accB[q] = 0ull;
        #pragma unroll 2
        for (int it = 0; it < HDIM / 16; ++it) {
            const int k = ks + (it << 4);
            ulonglong2 w = W2v[k * 16 + ig];
            #pragma unroll
            for (int r = 0; r < ROWS; ++r) {
                u64 hh = h_d[r * HPAD + k];
                accB[r * 2 + 0] = ffma2(hh, w.x, accB[r * 2 + 0]);
                accB[r * 2 + 1] = ffma2(hh, w.y, accB[r * 2 + 1]);
            }
        }
        #pragma unroll
        for (int r = 0; r < ROWS; ++r)
            *(ulonglong2*)&psd[ks * 256 + r * 32 + ig * 2] =
                make_ulonglong2(accB[r * 2], accB[r * 2 + 1]);
        __syncthreads();

        // ---- Epilogue: reduce partials, x update, stage next input ----
        {
            const int r  = rr;
            const int ip = lane;              // i pair (2ip, 2ip+1)
            u64 s = psd[r * 32 + ip];
            #pragma unroll
            for (int q = 1; q < 16; ++q)
                s = fadd2(s, psd[q * 256 + r * 32 + ip]);
            float2 sv = unpack2(s);
            const int i0 = 2 * ip, i1 = i0 + 1;
            float xo0 = unpack2(in_d[i0 * ROWS + r]).x;
            float xo1 = unpack2(in_d[i1 * ROWS + r]).x;
            float xn0 = xo0 + DTC * (sv.x + b2s[i0]);
            float xn1 = xo1 + DTC * (sv.y + b2s[i1]);
            in_d[i0 * ROWS + r] = pack2(xn0, xn0);
            in_d[i1 * ROWS + r] = pack2(xn1, xn1);
            *(float2*)&out[(size_t)(b0 + r) * (TSTEPS + 1) * SDIM
                           + (size_t)(t + 1) * SDIM + i0] = make_float2(xn0, xn1);
            if (t + 1 < TSTEPS)
                in_d[(SDIM + lane) * ROWS + r] = pack2(u_next, u_next);
        }
        __syncthreads();
    }
}

extern "C" void kernel_launch(void* const* d_in, const int* in_sizes, int n_in,
                              void* d_out, int out_size) {
    const float* x0       = (const float*)d_in[0];
    const float* controls = (const float*)d_in[1];
    const float* W1       = (const float*)d_in[2];
    const float* b1       = (const float*)d_in[3];
    const float* W2       = (const float*)d_in[4];
    const float* b2       = (const float*)d_in[5];
    float* out = (float*)d_out;

    static bool attr_set = false;
    if (!attr_set) {
        cudaFuncSetAttribute(rollout_kernel,
                             cudaFuncAttributeMaxDynamicSharedMemorySize,
                             (int)SMEM_BYTES);
        attr_set = true;
    }
    rollout_kernel<<<NBLK, NTHR, SMEM_BYTES>>>(x0, controls, W1, b1, W2, b2, out);
}

// round 4
// speedup vs baseline: 2.0386x; 2.0386x over previous
#include <cuda_runtime.h>
#include <cstdint>
#include <cstddef>

// x_{t+1} = x_t + 0.1*tanh([x_t,u_t]@W1 + b1)@W2 + b2
// B=1024, T=200, SD=64, CD=32, H=512. Persistent CTA per 8 batch rows.
// Phase A: batch-row pairs packed in f32x2 lanes, W1 read once per SM
// (32 k persistent in regs, 64 k software-pipelined LDG).
// Phase B: i-pairs in f32x2, h stored duplicated {h,h} with padded layout.

typedef unsigned long long u64;

static constexpr int   TSTEPS = 200;
static constexpr int   SDIM   = 64;
static constexpr int   CDIM   = 32;
static constexpr int   INDIM  = 96;
static constexpr int   HDIM   = 512;
static constexpr int   ROWS   = 8;
static constexpr int   NBLK   = 1024 / ROWS;   // 128
static constexpr int   NTHR   = 256;
static constexpr float DTC    = 0.1f;

static constexpr int   HROW   = 544;   // 512 k + 2 u64 pad per 32-k block

static constexpr int W2_U = HDIM * SDIM / 2;  // 16384 u64: W2 pairs [k][32]
static constexpr int H_U  = ROWS * HROW;      //  4352 u64: h dup {h,h}, padded k
static constexpr int IN_U = INDIM * 4;        //   384 u64: [k][rp] = {v_2rp, v_2rp+1}
static constexpr int PS_U = 16 * ROWS * 32;   //  4096 u64: partials [ks][r][ipair]
static constexpr size_t SMEM_BYTES =
    (size_t)(W2_U + H_U + IN_U + PS_U) * 8 + (size_t)SDIM * 4;  // 201,984 B

__device__ __forceinline__ u64 ffma2(u64 a, u64 b, u64 c) {
    u64 d;
    asm("fma.rn.f32x2 %0, %1, %2, %3;" : "=l"(d) : "l"(a), "l"(b), "l"(c));
    return d;
}
__device__ __forceinline__ u64 fadd2(u64 a, u64 b) {
    u64 d;
    asm("add.rn.f32x2 %0, %1, %2;" : "=l"(d) : "l"(a), "l"(b));
    return d;
}
__device__ __forceinline__ u64 pack2(float lo, float hi) {
    u64 d;
    asm("mov.b64 %0, {%1, %2};" : "=l"(d) : "r"(__float_as_int(lo)), "r"(__float_as_int(hi)));
    return d;
}
__device__ __forceinline__ u64 dupf(float f) {
    u64 d;
    asm("mov.b64 %0, {%1, %1};" : "=l"(d) : "r"(__float_as_int(f)));
    return d;
}
__device__ __forceinline__ float2 unpack2(u64 d) {
    int lo, hi;
    asm("mov.b64 {%0, %1}, %2;" : "=r"(lo), "=r"(hi) : "l"(d));
    return make_float2(__int_as_float(lo), __int_as_float(hi));
}

__device__ __forceinline__ float fast_tanh(float x) {
    float e = __expf(2.0f * x);
    return 1.0f - __fdividef(2.0f, e + 1.0f);
}

__global__ void __launch_bounds__(NTHR, 1)
rollout_kernel(const float* __restrict__ x0,
               const float* __restrict__ controls,
               const float* __restrict__ W1,
               const float* __restrict__ b1,
               const float* __restrict__ W2,
               const float* __restrict__ b2,
               float* __restrict__ out)
{
    extern __shared__ u64 sm[];
    u64*   W2d  = sm;              // [k][32] pairs {W2[k][2p], W2[k][2p+1]}
    u64*   h_d  = W2d + W2_U;      // [r][HROW] {h,h}, padded k index
    u64*   in_s = h_d + H_U;       // [k][rp] rowpair values
    u64*   psd  = in_s + IN_U;     // [ks][r][ipair]
    float* b2s  = (float*)(psd + PS_U);
    float* in_f = (float*)in_s;    // float idx = k*8 + r

    const int tid  = threadIdx.x;
    const int lane = tid & 31;
    const int wid  = tid >> 5;     // row for staging/epilogue
    const int b0   = blockIdx.x * ROWS;
    const int ks   = tid >> 4;     // phase B k-split 0..15
    const int ig   = tid & 15;     // phase B i-group (2 pairs = 4 i)

    // ---- prologue ----
    {
        const float4* src = (const float4*)W2;
        float4* dst = (float4*)W2d;
        for (int i = tid; i < (HDIM * SDIM) / 4; i += NTHR) dst[i] = src[i];
    }
    if (tid < SDIM) b2s[tid] = b2[tid];

    float2 b1v = ((const float2*)b1)[tid];   // cols 2tid, 2tid+1
    const u64 b1d0 = dupf(b1v.x);
    const u64 b1d1 = dupf(b1v.y);

    // stage x0, u(0); emit states[:,0,:]
    {
        const int gb = b0 + wid;
        float xa = x0[gb * SDIM + lane];
        float xb = x0[gb * SDIM + lane + 32];
        in_f[lane * 8 + wid]        = xa;
        in_f[(lane + 32) * 8 + wid] = xb;
        size_t ob = (size_t)gb * (TSTEPS + 1) * SDIM;
        out[ob + lane]      = xa;
        out[ob + lane + 32] = xb;
        in_f[(SDIM + lane) * 8 + wid] =
            controls[(size_t)gb * TSTEPS * CDIM + lane];
    }
    __syncthreads();

    const float2* W1f = (const float2*)W1;   // [k][256 col-pairs]; thread owns pair=tid
    const ulonglong2* W2v = (const ulonglong2*)W2d;

    // persistent W1 k=0..31 (step-invariant, lives in registers all kernel)
    float2 wper[32];
    #pragma unroll
    for (int kk = 0; kk < 32; ++kk) wper[kk] = W1f[kk * 256 + tid];

    // double-buffered streamed W1 blocks (k = 32..95 in 4 blocks of 16)
    float2 wbuf[2][16];
    #pragma unroll
    for (int kk = 0; kk < 16; ++kk) wbuf[0][kk] = W1f[(32 + kk) * 256 + tid];

    const int hkp = 2 * tid + ((2 * tid) >> 5) * 2;  // padded h index for col 2tid

    for (int t = 0; t < TSTEPS; ++t) {
        float u_next = 0.0f;
        if (t + 1 < TSTEPS)
            u_next = controls[(size_t)(b0 + wid) * TSTEPS * CDIM
                              + (size_t)(t + 1) * CDIM + lane];

        // ---- Phase A: acc{r,r+1}[c] += in{r,r+1}[k] * {w,w} ----
        u64 acc[8];
        acc[0] = b1d0; acc[1] = b1d0; acc[2] = b1d0; acc[3] = b1d0;
        acc[4] = b1d1; acc[5] = b1d1; acc[6] = b1d1; acc[7] = b1d1;

        #pragma unroll
        for (int kk = 0; kk < 32; ++kk) {
            ulonglong2 uA = *(const ulonglong2*)&in_s[kk * 4];
            ulonglong2 uB = *(const ulonglong2*)&in_s[kk * 4 + 2];
            u64 w0 = dupf(wper[kk].x);
            u64 w1 = dupf(wper[kk].y);
            acc[0] = ffma2(uA.x, w0, acc[0]);
            acc[1] = ffma2(uA.y, w0, acc[1]);
            acc[2] = ffma2(uB.x, w0, acc[2]);
            acc[3] = ffma2(uB.y, w0, acc[3]);
            acc[4] = ffma2(uA.x, w1, acc[4]);
            acc[5] = ffma2(uA.y, w1, acc[5]);
            acc[6] = ffma2(uB.x, w1, acc[6]);
            acc[7] = ffma2(uB.y, w1, acc[7]);
        }
        #pragma unroll
        for (int blk = 0; blk < 4; ++blk) {
            const int cur = blk & 1;
            // prefetch next block (last block prefetches k=32 for NEXT step)
            const int knext = (blk < 3) ? (48 + 16 * blk) : 32;
            #pragma unroll
            for (int kk = 0; kk < 16; ++kk)
                wbuf[cur ^ 1][kk] = W1f[(knext + kk) * 256 + tid];
            #pragma unroll
            for (int kk = 0; kk < 16; ++kk) {
                const int k = 32 + blk * 16 + kk;
                ulonglong2 uA = *(const ulonglong2*)&in_s[k * 4];
                ulonglong2 uB = *(const ulonglong2*)&in_s[k * 4 + 2];
                u64 w0 = dupf(wbuf[cur][kk].x);
                u64 w1 = dupf(wbuf[cur][kk].y);
                acc[0] = ffma2(uA.x, w0, acc[0]);
                acc[1] = ffma2(uA.y, w0, acc[1]);
                acc[2] = ffma2(uB.x, w0, acc[2]);
                acc[3] = ffma2(uB.y, w0, acc[3]);
                acc[4] = ffma2(uA.x, w1, acc[4]);
                acc[5] = ffma2(uA.y, w1, acc[5]);
                acc[6] = ffma2(uB.x, w1, acc[6]);
                acc[7] = ffma2(uB.y, w1, acc[7]);
            }
        }
        // tanh + store duplicated {h,h} (cols 2tid, 2tid+1 per row)
        #pragma unroll
        for (int rp = 0; rp < 4; ++rp) {
            float2 a0 = unpack2(acc[rp]);       // col c0: rows 2rp, 2rp+1
            float2 a1 = unpack2(acc[4 + rp]);   // col c1
            float t00 = fast_tanh(a0.x), t10 = fast_tanh(a1.x);
            float t01 = fast_tanh(a0.y), t11 = fast_tanh(a1.y);
            *(ulonglong2*)&h_d[(2 * rp) * HROW + hkp] =
                make_ulonglong2(pack2(t00, t00), pack2(t10, t10));
            *(ulonglong2*)&h_d[(2 * rp + 1) * HROW + hkp] =
                make_ulonglong2(pack2(t01, t01), pack2(t11, t11));
        }
        __syncthreads();

        // ---- Phase B: acc{i0,i1}[r] += {h,h}[r][k] * {w_i0, w_i1} ----
        u64 accB[16];
        #pragma unroll
        for (int q = 0; q < 16; ++q) accB[q] = 0ull;
        const int hbase = ks * 34;   // padded base of this thread's 32-k strip
        #pragma unroll 4
        for (int q = 0; q < 16; ++q) {
            const int k0 = ks * 32 + 2 * q;
            ulonglong2 wA = W2v[k0 * 16 + ig];
            ulonglong2 wB = W2v[(k0 + 1) * 16 + ig];
            #pragma unroll
            for (int r = 0; r < ROWS; ++r) {
                ulonglong2 hh = *(const ulonglong2*)&h_d[r * HROW + hbase + 2 * q];
                accB[r * 2 + 0] = ffma2(hh.x, wA.x, accB[r * 2 + 0]);
                accB[r * 2 + 1] = ffma2(hh.x, wA.y, accB[r * 2 + 1]);
                accB[r * 2 + 0] = ffma2(hh.y, wB.x, accB[r * 2 + 0]);
                accB[r * 2 + 1] = ffma2(hh.y, wB.y, accB[r * 2 + 1]);
            }
        }
        #pragma unroll
        for (int r = 0; r < ROWS; ++r)
            *(ulonglong2*)&psd[ks * 256 + r * 32 + ig * 2] =
                make_ulonglong2(accB[r * 2], accB[r * 2 + 1]);
        __syncthreads();

        // ---- Epilogue: tree-reduce 16 partials, x update, stage next input ----
        {
            const int r  = wid;
            const int ip = lane;          // i-pair (2ip, 2ip+1)
            u64 p[16];
            #pragma unroll
            for (int q = 0; q < 16; ++q) p[q] = psd[q * 256 + r * 32 + ip];
            #pragma unroll
            for (int q = 0; q < 8; ++q)  p[q] = fadd2(p[q], p[q + 8]);
            #pragma unroll
            for (int q = 0; q < 4; ++q)  p[q] = fadd2(p[q], p[q + 4]);
            p[0] = fadd2(fadd2(p[0], p[2]), fadd2(p[1], p[3]));
            float2 sv = unpack2(p[0]);
            const int i0 = 2 * ip, i1 = i0 + 1;
            float xo0 = in_f[i0 * 8 + r];
            float xo1 = in_f[i1 * 8 + r];
            float xn0 = xo0 + DTC * (sv.x + b2s[i0]);
            float xn1 = xo1 + DTC * (sv.y + b2s[i1]);
            in_f[i0 * 8 + r] = xn0;
            in_f[i1 * 8 + r] = xn1;
            *(float2*)&out[(size_t)(b0 + r) * (TSTEPS + 1) * SDIM
                           + (size_t)(t + 1) * SDIM + i0] = make_float2(xn0, xn1);
            if (t + 1 < TSTEPS)
                in_f[(SDIM + lane) * 8 + r] = u_next;
        }
        __syncthreads();
    }
}

extern "C" void kernel_launch(void* const* d_in, const int* in_sizes, int n_in,
                              void* d_out, int out_size) {
    const float* x0       = (const float*)d_in[0];
    const float* controls = (const float*)d_in[1];
    const float* W1       = (const float*)d_in[2];
    const float* b1       = (const float*)d_in[3];
    const float* W2       = (const float*)d_in[4];
    const float* b2       = (const float*)d_in[5];
    float* out = (float*)d_out;

    static bool attr_set = false;
    if (!attr_set) {
        cudaFuncSetAttribute(rollout_kernel,
                             cudaFuncAttributeMaxDynamicSharedMemorySize,
                             (int)SMEM_BYTES);
        attr_set = true;
    }
    rollout_kernel<<<NBLK, NTHR, SMEM_BYTES>>>(x0, controls, W1, b1, W2, b2, out);
}